// round 7
// baseline (speedup 1.0000x reference)
#include <cuda_runtime.h>
#include <cuda_bf16.h>
#include <cstdint>

// Problem constants (fixed by the reference)
#define NN   10000
#define EE   160000
#define FIN  512
#define FH   512
#define FOUT 16

// ---------------------------------------------------------------------------
// Scratch (no allocations allowed -> __device__ globals). Kernels reference
// these directly — NO cudaGetSymbolAddress (it broke graph capture in R2).
// ---------------------------------------------------------------------------
__device__ float g_h[NN * FH];        // GEMM output (X @ W)
__device__ float g_pre[NN * FH];      // aggregated pre-activation
__device__ float g_dinv[NN];
__device__ int   g_count[NN];
__device__ int   g_cursor[NN];
__device__ int   g_rowptr[NN + 1];
__device__ int   g_col[EE];           // src node per CSR-sorted edge
__device__ int   g_src[EE];           // decoded edge endpoints
__device__ int   g_dst[EE];
__device__ int   g_is64;              // 1 if edge_index buffer is int64

// ---------------------------------------------------------------------------
// f32x2 helpers (Blackwell packed fp32 FMA — only via PTX)
// ---------------------------------------------------------------------------
__device__ __forceinline__ unsigned long long fma2(unsigned long long a,
                                                   unsigned long long b,
                                                   unsigned long long c) {
    unsigned long long d;
    asm("fma.rn.f32x2 %0, %1, %2, %3;" : "=l"(d) : "l"(a), "l"(b), "l"(c));
    return d;
}
__device__ __forceinline__ unsigned long long pack2(float x) {
    unsigned long long d;
    asm("mov.b64 %0, {%1, %1};" : "=l"(d) : "r"(__float_as_uint(x)));
    return d;
}

// ---------------------------------------------------------------------------
// Edge-index dtype detection.
// Probe odd 32-bit words in [0, 2E): for int64 data these are high halves of
// nonneg values < 2^31 -> all exactly 0. For int32 data they are random node
// ids in [0,10000) -> ~all nonzero. 256 probes make misdetection impossible.
// (Words [0,2E) are in-bounds for BOTH dtypes: int32 total = 2E words.)
// ---------------------------------------------------------------------------
__global__ void detect_kernel(const int* __restrict__ w) {
    __shared__ int nz;
    if (threadIdx.x == 0) nz = 0;
    __syncthreads();
    if (w[2 * threadIdx.x + 1] != 0) atomicOr(&nz, 1);
    __syncthreads();
    if (threadIdx.x == 0) g_is64 = (nz == 0) ? 1 : 0;
}

// ---------------------------------------------------------------------------
// CSR build
// ---------------------------------------------------------------------------
__global__ void init_counts_kernel() {
    int i = blockIdx.x * blockDim.x + threadIdx.x;
    if (i < NN) { g_count[i] = 0; g_cursor[i] = 0; }
}

// decode edges (dtype-dispatched) + degree histogram, with clamps so no
// input can cause an OOB access.
__global__ void decode_count_kernel(const void* __restrict__ ei) {
    int e = blockIdx.x * blockDim.x + threadIdx.x;
    if (e < EE) {
        int src, dst;
        if (g_is64) {
            const long long* p = (const long long*)ei;
            src = (int)p[e];
            dst = (int)p[EE + e];
        } else {
            const int* p = (const int*)ei;
            src = p[e];
            dst = p[EE + e];
        }
        src = min(max(src, 0), NN - 1);
        dst = min(max(dst, 0), NN - 1);
        g_src[e] = src;
        g_dst[e] = dst;
        atomicAdd(&g_count[dst], 1);
    }
}

// single-block exclusive scan over g_count -> g_rowptr
__global__ void scan_kernel() {
    __shared__ int sums[1024];
    const int t = threadIdx.x;
    const int CH = (NN + 1023) / 1024;   // 10
    int base = t * CH;
    int s = 0;
    for (int i = 0; i < CH; i++) {
        int idx = base + i;
        if (idx < NN) s += g_count[idx];
    }
    sums[t] = s;
    __syncthreads();
    // Hillis–Steele inclusive scan (double-buffered via two syncs)
    for (int off = 1; off < 1024; off *= 2) {
        int v = (t >= off) ? sums[t - off] : 0;
        __syncthreads();
        sums[t] += v;
        __syncthreads();
    }
    int run = (t == 0) ? 0 : sums[t - 1];
    for (int i = 0; i < CH; i++) {
        int idx = base + i;
        if (idx < NN) { g_rowptr[idx] = run; run += g_count[idx]; }
    }
    if (t == 1023) g_rowptr[NN] = run;
}

__global__ void dinv_kernel() {
    int i = blockIdx.x * blockDim.x + threadIdx.x;
    if (i < NN) g_dinv[i] = rsqrtf((float)g_count[i] + 1.0f);
}

__global__ void fill_edges_kernel() {
    int e = blockIdx.x * blockDim.x + threadIdx.x;
    if (e < EE) {
        int dst = g_dst[e];
        int pos = atomicAdd(&g_cursor[dst], 1);
        g_col[g_rowptr[dst] + pos] = g_src[e];
    }
}

// ---------------------------------------------------------------------------
// GEMM: g_h[M,512] = act(A[M,512]) @ B[512,512]
// A_FROM_PRE: read A from g_pre (device global) instead of the pointer param.
// 128x128 tile, BK=8, 256 threads, 8x8 per-thread, f32x2 accumulation.
// ---------------------------------------------------------------------------
template <bool RELU, bool A_FROM_PRE>
__global__ __launch_bounds__(256, 2)
void gemm_kernel(const float* __restrict__ Aext, const float* __restrict__ B,
                 int M) {
    __shared__ __align__(16) float As[8][128];   // A^T tile: As[k][row]
    __shared__ __align__(16) float Bs[8][128];   // Bs[k][col]

    const float* __restrict__ A = A_FROM_PRE ? g_pre : Aext;
    float* __restrict__ C = g_h;

    const int tid = threadIdx.x;
    const int tx = tid & 15;        // 0..15 -> col group
    const int ty = tid >> 4;        // 0..15 -> row group
    const int rowBase = blockIdx.x * 128;
    const int colBase = blockIdx.y * 128;

    // A-load coords: each thread loads one float4 (128 rows x 8 cols)
    const int aRow = tid >> 1;            // 0..127
    const int aCol = (tid & 1) * 4;       // 0 or 4
    // B-load coords: 8 rows x 128 cols
    const int bRow = tid >> 5;            // 0..7
    const int bCol = (tid & 31) * 4;      // 0..124

    unsigned long long acc[8][4];
#pragma unroll
    for (int i = 0; i < 8; i++)
#pragma unroll
        for (int j = 0; j < 4; j++) acc[i][j] = 0ULL;

    const int gRow = rowBase + aRow;

    for (int k0 = 0; k0 < 512; k0 += 8) {
        // load A tile (transposed into As) with optional ReLU
        float4 av = make_float4(0.f, 0.f, 0.f, 0.f);
        if (gRow < M)
            av = *reinterpret_cast<const float4*>(&A[(size_t)gRow * 512 + k0 + aCol]);
        if (RELU) {
            av.x = fmaxf(av.x, 0.f); av.y = fmaxf(av.y, 0.f);
            av.z = fmaxf(av.z, 0.f); av.w = fmaxf(av.w, 0.f);
        }
        As[aCol + 0][aRow] = av.x;
        As[aCol + 1][aRow] = av.y;
        As[aCol + 2][aRow] = av.z;
        As[aCol + 3][aRow] = av.w;

        // load B tile
        float4 bv = *reinterpret_cast<const float4*>(
            &B[(size_t)(k0 + bRow) * 512 + colBase + bCol]);
        *reinterpret_cast<float4*>(&Bs[bRow][bCol]) = bv;

        __syncthreads();

#pragma unroll
        for (int k = 0; k < 8; k++) {
            float4 a0 = *reinterpret_cast<const float4*>(&As[k][ty * 8]);
            float4 a1 = *reinterpret_cast<const float4*>(&As[k][ty * 8 + 4]);
            ulonglong2 b0 = *reinterpret_cast<const ulonglong2*>(&Bs[k][tx * 8]);
            ulonglong2 b1 = *reinterpret_cast<const ulonglong2*>(&Bs[k][tx * 8 + 4]);
            unsigned long long bb[4] = {b0.x, b0.y, b1.x, b1.y};
            float aa[8] = {a0.x, a0.y, a0.z, a0.w, a1.x, a1.y, a1.z, a1.w};
#pragma unroll
            for (int i = 0; i < 8; i++) {
                unsigned long long a2 = pack2(aa[i]);
#pragma unroll
                for (int j = 0; j < 4; j++)
                    acc[i][j] = fma2(a2, bb[j], acc[i][j]);
            }
        }
        __syncthreads();
    }

    // store
#pragma unroll
    for (int i = 0; i < 8; i++) {
        int row = rowBase + ty * 8 + i;
        if (row < M) {
            ulonglong2 v0, v1;
            v0.x = acc[i][0]; v0.y = acc[i][1];
            v1.x = acc[i][2]; v1.y = acc[i][3];
            *reinterpret_cast<ulonglong2*>(&C[(size_t)row * 512 + colBase + tx * 8]) = v0;
            *reinterpret_cast<ulonglong2*>(&C[(size_t)row * 512 + colBase + tx * 8 + 4]) = v1;
        }
    }
}

// ---------------------------------------------------------------------------
// Aggregation: g_pre[i] = dinv[i]^2*g_h[i] + b + sum_{e:dst=i} dinv[i]*dinv[s]*g_h[s]
// One block (128 threads) per node; pure reads (no fp atomics), h fits in L2.
// ---------------------------------------------------------------------------
__global__ __launch_bounds__(128)
void aggregate_kernel(const float* __restrict__ bias) {
    const float* __restrict__ h = g_h;
    float* __restrict__ out = g_pre;

    const int i = blockIdx.x;
    const int f = threadIdx.x * 4;
    const float di = g_dinv[i];

    float4 hv = *reinterpret_cast<const float4*>(&h[(size_t)i * 512 + f]);
    float4 bv = *reinterpret_cast<const float4*>(&bias[f]);
    const float w0 = di * di;
    float4 acc;
    acc.x = fmaf(w0, hv.x, bv.x);
    acc.y = fmaf(w0, hv.y, bv.y);
    acc.z = fmaf(w0, hv.z, bv.z);
    acc.w = fmaf(w0, hv.w, bv.w);

    const int s0 = g_rowptr[i];
    const int s1 = g_rowptr[i + 1];
    for (int e = s0; e < s1; e++) {
        int s = g_col[e];                 // broadcast load
        float w = di * g_dinv[s];
        float4 v = *reinterpret_cast<const float4*>(&h[(size_t)s * 512 + f]);
        acc.x = fmaf(w, v.x, acc.x);
        acc.y = fmaf(w, v.y, acc.y);
        acc.z = fmaf(w, v.z, acc.z);
        acc.w = fmaf(w, v.w, acc.w);
    }
    *reinterpret_cast<float4*>(&out[(size_t)i * 512 + f]) = acc;
}

// ---------------------------------------------------------------------------
// Final: out[N,16] = relu(g_pre) @ Wl + bl. Wl staged in smem; warp per row.
// ---------------------------------------------------------------------------
__global__ __launch_bounds__(256)
void final_kernel(const float* __restrict__ Wl, const float* __restrict__ bl,
                  float* __restrict__ out) {
    __shared__ __align__(16) float WlS[512 * 16];   // 32 KB
    __shared__ float outS[8][16];
    const float* __restrict__ pre = g_pre;

    const int tid = threadIdx.x;
    // stage Wl
    for (int idx = tid; idx < 512 * 16 / 4; idx += 256)
        reinterpret_cast<float4*>(WlS)[idx] =
            reinterpret_cast<const float4*>(Wl)[idx];
    __syncthreads();

    const int w = tid >> 5;
    const int lane = tid & 31;
    const int row = blockIdx.x * 8 + w;
    if (row < NN) {
        float4 acc0 = make_float4(0.f, 0.f, 0.f, 0.f);
        float4 acc1 = acc0, acc2 = acc0, acc3 = acc0;
#pragma unroll
        for (int kk = 0; kk < 16; kk++) {
            int k = kk * 32 + lane;
            float a = fmaxf(pre[(size_t)row * 512 + k], 0.f);
            const float4* wrow = reinterpret_cast<const float4*>(&WlS[k * 16]);
            float4 w0 = wrow[0], w1 = wrow[1], w2 = wrow[2], w3 = wrow[3];
            acc0.x = fmaf(a, w0.x, acc0.x); acc0.y = fmaf(a, w0.y, acc0.y);
            acc0.z = fmaf(a, w0.z, acc0.z); acc0.w = fmaf(a, w0.w, acc0.w);
            acc1.x = fmaf(a, w1.x, acc1.x); acc1.y = fmaf(a, w1.y, acc1.y);
            acc1.z = fmaf(a, w1.z, acc1.z); acc1.w = fmaf(a, w1.w, acc1.w);
            acc2.x = fmaf(a, w2.x, acc2.x); acc2.y = fmaf(a, w2.y, acc2.y);
            acc2.z = fmaf(a, w2.z, acc2.z); acc2.w = fmaf(a, w2.w, acc2.w);
            acc3.x = fmaf(a, w3.x, acc3.x); acc3.y = fmaf(a, w3.y, acc3.y);
            acc3.z = fmaf(a, w3.z, acc3.z); acc3.w = fmaf(a, w3.w, acc3.w);
        }
        // butterfly reduce all 16 accumulators across the warp
#pragma unroll
        for (int off = 16; off > 0; off >>= 1) {
            acc0.x += __shfl_xor_sync(0xffffffff, acc0.x, off);
            acc0.y += __shfl_xor_sync(0xffffffff, acc0.y, off);
            acc0.z += __shfl_xor_sync(0xffffffff, acc0.z, off);
            acc0.w += __shfl_xor_sync(0xffffffff, acc0.w, off);
            acc1.x += __shfl_xor_sync(0xffffffff, acc1.x, off);
            acc1.y += __shfl_xor_sync(0xffffffff, acc1.y, off);
            acc1.z += __shfl_xor_sync(0xffffffff, acc1.z, off);
            acc1.w += __shfl_xor_sync(0xffffffff, acc1.w, off);
            acc2.x += __shfl_xor_sync(0xffffffff, acc2.x, off);
            acc2.y += __shfl_xor_sync(0xffffffff, acc2.y, off);
            acc2.z += __shfl_xor_sync(0xffffffff, acc2.z, off);
            acc2.w += __shfl_xor_sync(0xffffffff, acc2.w, off);
            acc3.x += __shfl_xor_sync(0xffffffff, acc3.x, off);
            acc3.y += __shfl_xor_sync(0xffffffff, acc3.y, off);
            acc3.z += __shfl_xor_sync(0xffffffff, acc3.z, off);
            acc3.w += __shfl_xor_sync(0xffffffff, acc3.w, off);
        }
        if (lane == 0) {
            *reinterpret_cast<float4*>(&outS[w][0])  = acc0;
            *reinterpret_cast<float4*>(&outS[w][4])  = acc1;
            *reinterpret_cast<float4*>(&outS[w][8])  = acc2;
            *reinterpret_cast<float4*>(&outS[w][12]) = acc3;
        }
        __syncwarp();
        if (lane < 16)
            out[(size_t)row * 16 + lane] = outS[w][lane] + bl[lane];
    }
}

// ---------------------------------------------------------------------------
// Launch — pure kernel launches, no runtime API calls (graph-capture safe)
// ---------------------------------------------------------------------------
extern "C" void kernel_launch(void* const* d_in, const int* in_sizes, int n_in,
                              void* d_out, int out_size) {
    const float* x  = (const float*)d_in[0];
    const void*  ei = d_in[1];                 // int32 OR int64, detected on device
    const float* W1 = (const float*)d_in[2];
    const float* b1 = (const float*)d_in[3];
    const float* W2 = (const float*)d_in[4];
    const float* b2 = (const float*)d_in[5];
    const float* Wl = (const float*)d_in[6];
    const float* bl = (const float*)d_in[7];
    float* out = (float*)d_out;

    // CSR build + degrees
    detect_kernel<<<1, 256>>>((const int*)ei);
    init_counts_kernel<<<(NN + 255) / 256, 256>>>();
    decode_count_kernel<<<(EE + 255) / 256, 256>>>(ei);
    scan_kernel<<<1, 1024>>>();
    dinv_kernel<<<(NN + 255) / 256, 256>>>();
    fill_edges_kernel<<<(EE + 255) / 256, 256>>>();

    dim3 gemmGrid((NN + 127) / 128, 512 / 128);

    // Layer 1: g_h = x @ W1 ; g_pre = agg(g_h) + b1
    gemm_kernel<false, false><<<gemmGrid, 256>>>(x, W1, NN);
    aggregate_kernel<<<NN, 128>>>(b1);
    // Layer 2: g_h = relu(g_pre) @ W2 ; g_pre = agg(g_h) + b2
    gemm_kernel<true, true><<<gemmGrid, 256>>>(nullptr, W2, NN);
    aggregate_kernel<<<NN, 128>>>(b2);
    // Classifier
    final_kernel<<<(NN + 7) / 8, 256>>>(Wl, bl, out);
}

// round 13
// speedup vs baseline: 1.1269x; 1.1269x over previous
#include <cuda_runtime.h>
#include <cuda_bf16.h>
#include <cstdint>

// Problem constants (fixed by the reference)
#define NN   10000
#define EE   160000
#define MPAD 10240            // 80 * 128 rows (padded M)
#define KE   1536             // extended K: [hi | lo | hi] * 512
#define KE2  768              // KE in bf16x2 units

// ---------------------------------------------------------------------------
// Scratch (__device__ globals; no allocations, no cudaGetSymbolAddress)
// ---------------------------------------------------------------------------
__device__ float g_h[NN * 512];        // GEMM output (fp32)
__device__ float g_pre[NN * 512];      // layer-2 aggregated pre-activation
__device__ float g_dinv[NN];
__device__ int   g_count[NN];
__device__ int   g_cursor[NN];
__device__ int   g_rowptr[NN + 1];
__device__ int   g_col[EE];
__device__ int   g_src[EE];
__device__ int   g_dst[EE];
__device__ int   g_is64;
// bf16 split operands. A pattern along K: [hiA | loA | hiA]
// B pattern along K: [hiB | hiB | loB]  =>  sum = hi*hi + lo*hi + hi*lo
__device__ __align__(16) __nv_bfloat162 g_A2[(size_t)MPAD * KE2];   // ~31.5 MB
__device__ __align__(16) __nv_bfloat162 g_B1[(size_t)512 * KE2];
__device__ __align__(16) __nv_bfloat162 g_B2[(size_t)512 * KE2];

// ---------------------------------------------------------------------------
// Warp-MMA helpers (baseline PTX: ldmatrix sm_75+, mma.sync bf16 sm_80+ —
// NO sm_103a-gated instructions; R8 showed the harness emits compute_103).
// ---------------------------------------------------------------------------
__device__ __forceinline__ uint32_t smem_u32(const void* p) {
    uint32_t a;
    asm("{ .reg .u64 t; cvta.to.shared.u64 t, %1; cvt.u32.u64 %0, t; }"
        : "=r"(a) : "l"(p));
    return a;
}
__device__ __forceinline__ void ldm_x4(uint32_t& r0, uint32_t& r1,
                                       uint32_t& r2, uint32_t& r3, uint32_t a) {
    asm volatile("ldmatrix.sync.aligned.m8n8.x4.shared.b16 {%0,%1,%2,%3}, [%4];"
                 : "=r"(r0), "=r"(r1), "=r"(r2), "=r"(r3) : "r"(a));
}
__device__ __forceinline__ void mma16816(float* c, const uint32_t* a,
                                         const uint32_t* b) {
    asm volatile(
        "mma.sync.aligned.m16n8k16.row.col.f32.bf16.bf16.f32 "
        "{%0,%1,%2,%3}, {%4,%5,%6,%7}, {%8,%9}, {%0,%1,%2,%3};"
        : "+f"(c[0]), "+f"(c[1]), "+f"(c[2]), "+f"(c[3])
        : "r"(a[0]), "r"(a[1]), "r"(a[2]), "r"(a[3]), "r"(b[0]), "r"(b[1]));
}
__device__ __forceinline__ uint32_t swz128(uint32_t off) {
    return off ^ ((off >> 3) & 0x70);
}

// ---------------------------------------------------------------------------
// Edge-index dtype detection (int64 vs silently-int32 from JAX x64-off)
// ---------------------------------------------------------------------------
__global__ void detect_kernel(const int* __restrict__ w) {
    __shared__ int nz;
    if (threadIdx.x == 0) nz = 0;
    __syncthreads();
    if (w[2 * threadIdx.x + 1] != 0) atomicOr(&nz, 1);
    __syncthreads();
    if (threadIdx.x == 0) g_is64 = (nz == 0) ? 1 : 0;
}

// ---------------------------------------------------------------------------
// CSR build
// ---------------------------------------------------------------------------
__global__ void init_counts_kernel() {
    int i = blockIdx.x * blockDim.x + threadIdx.x;
    if (i < NN) { g_count[i] = 0; g_cursor[i] = 0; }
}

__global__ void decode_count_kernel(const void* __restrict__ ei) {
    int e = blockIdx.x * blockDim.x + threadIdx.x;
    if (e < EE) {
        int src, dst;
        if (g_is64) {
            const long long* p = (const long long*)ei;
            src = (int)p[e];  dst = (int)p[EE + e];
        } else {
            const int* p = (const int*)ei;
            src = p[e];  dst = p[EE + e];
        }
        src = min(max(src, 0), NN - 1);
        dst = min(max(dst, 0), NN - 1);
        g_src[e] = src;  g_dst[e] = dst;
        atomicAdd(&g_count[dst], 1);
    }
}

// warp-shuffle based exclusive scan
__global__ void scan_kernel() {
    __shared__ int wsum[32];
    const int t = threadIdx.x, lane = t & 31, wid = t >> 5;
    const int base = t * 10;
    int c[10], s = 0;
#pragma unroll
    for (int i = 0; i < 10; i++) {
        int idx = base + i;
        c[i] = (idx < NN) ? g_count[idx] : 0;
        s += c[i];
    }
    int incl = s;
#pragma unroll
    for (int off = 1; off < 32; off <<= 1) {
        int v = __shfl_up_sync(0xffffffffu, incl, off);
        if (lane >= off) incl += v;
    }
    if (lane == 31) wsum[wid] = incl;
    __syncthreads();
    if (wid == 0) {
        int w = wsum[lane];
#pragma unroll
        for (int off = 1; off < 32; off <<= 1) {
            int v = __shfl_up_sync(0xffffffffu, w, off);
            if (lane >= off) w += v;
        }
        wsum[lane] = w;
    }
    __syncthreads();
    int off = (wid ? wsum[wid - 1] : 0) + incl - s;
#pragma unroll
    for (int i = 0; i < 10; i++) {
        int idx = base + i;
        if (idx < NN) { g_rowptr[idx] = off; off += c[i]; }
    }
    if (t == 1023) g_rowptr[NN] = off;
}

__global__ void dinv_kernel() {
    int i = blockIdx.x * blockDim.x + threadIdx.x;
    if (i < NN) g_dinv[i] = rsqrtf((float)g_count[i] + 1.0f);
}

__global__ void fill_edges_kernel() {
    int e = blockIdx.x * blockDim.x + threadIdx.x;
    if (e < EE) {
        int dst = g_dst[e];
        int pos = atomicAdd(&g_cursor[dst], 1);
        g_col[g_rowptr[dst] + pos] = g_src[e];
    }
}

// ---------------------------------------------------------------------------
// Conversions: fp32 -> bf16 hi/lo split, laid out along extended K
// ---------------------------------------------------------------------------
__device__ __forceinline__ void split2(float a0, float a1,
                                       __nv_bfloat162& hh, __nv_bfloat162& ll) {
    __nv_bfloat16 h0 = __float2bfloat16(a0), h1 = __float2bfloat16(a1);
    __nv_bfloat16 l0 = __float2bfloat16(a0 - __bfloat162float(h0));
    __nv_bfloat16 l1 = __float2bfloat16(a1 - __bfloat162float(h1));
    hh = __halves2bfloat162(h0, h1);
    ll = __halves2bfloat162(l0, l1);
}

// x[10000,512] -> g_A2 rows [0,10240): pattern [hi | lo | hi], pad rows = 0
__global__ void convx_kernel(const float* __restrict__ x) {
    int i = blockIdx.x * 256 + threadIdx.x;       // pair index
    int row = i >> 8, cp = i & 255;
    float a0 = 0.f, a1 = 0.f;
    if (row < NN) {
        float2 v = ((const float2*)x)[(size_t)row * 256 + cp];
        a0 = v.x; a1 = v.y;
    }
    __nv_bfloat162 hh, ll;
    split2(a0, a1, hh, ll);
    size_t b = (size_t)row * KE2 + cp;
    g_A2[b] = hh; g_A2[b + 256] = ll; g_A2[b + 512] = hh;
}

// W[512,512] (k-major rows) -> Bsel[n][k] transposed split: [hi | hi | lo]
template <int WHICH>   // 1 -> g_B1, 2 -> g_B2
__global__ void convw_kernel(const float* __restrict__ W) {
    __nv_bfloat162* out = (WHICH == 1) ? g_B1 : g_B2;
    int i = blockIdx.x * 256 + threadIdx.x;       // (n, kp)
    int n = i >> 8, kp = i & 255;
    float a0 = W[(size_t)(2 * kp) * 512 + n];
    float a1 = W[(size_t)(2 * kp + 1) * 512 + n];
    __nv_bfloat162 hh, ll;
    split2(a0, a1, hh, ll);
    size_t b = (size_t)n * KE2 + kp;
    out[b] = hh; out[b + 256] = hh; out[b + 512] = ll;
}

// ---------------------------------------------------------------------------
// Warp-MMA GEMM: g_h[M,512] = A2 @ B^T over extended K=1536 (bf16 split)
// CTA: 128x128 tile, 256 threads / 8 warps, warp tile 64x32 (4x4 m16n8k16).
// 24 K-chunks of 64 bf16 staged in SW128-swizzled SMEM, ldmatrix operands.
// ---------------------------------------------------------------------------
template <int WHICH>   // weight select: 1 -> g_B1, 2 -> g_B2
__global__ __launch_bounds__(256)
void gemm_mma_kernel() {
    __shared__ __align__(1024) char sm[32768];    // As 16KB | Bs 16KB
    char* const pA = sm;
    char* const pB = sm + 16384;
    const __nv_bfloat162* __restrict__ Bsel = (WHICH == 1) ? g_B1 : g_B2;

    const int tid = threadIdx.x;
    const int lane = tid & 31, wid = tid >> 5;
    const int warp_m = wid & 1;       // 2 m-blocks of 64
    const int warp_n = wid >> 1;      // 4 n-blocks of 32
    const int rowBase = blockIdx.x * 128;
    const int colBase = blockIdx.y * 128;

    // Cooperative load: threads 0-127 -> A rows, 128-255 -> B rows.
    const int half = tid >> 7;
    const int lrow = tid & 127;
    const uint4* __restrict__ gsrc = half
        ? (const uint4*)(Bsel + (size_t)(colBase + lrow) * KE2)
        : (const uint4*)(g_A2 + (size_t)(rowBase + lrow) * KE2);
    char* const sdst = half ? pB : pA;

    const uint32_t sA = smem_u32(pA);
    const uint32_t sB = smem_u32(pB);

    float acc[4][4][4];
#pragma unroll
    for (int i = 0; i < 4; i++)
#pragma unroll
        for (int j = 0; j < 4; j++)
#pragma unroll
            for (int r = 0; r < 4; r++) acc[i][j][r] = 0.f;

    for (int c = 0; c < 24; c++) {
#pragma unroll
        for (int j = 0; j < 8; j++) {                 // 128B per row
            uint4 v = gsrc[c * 8 + j];
            *(uint4*)(sdst + swz128((uint32_t)(lrow * 128 + j * 16))) = v;
        }
        __syncthreads();

#pragma unroll
        for (int ks = 0; ks < 4; ks++) {              // 4 x K=16
            const uint32_t kOff = ks * 32 + ((lane >> 4) * 16);
            uint32_t a[4][4];
#pragma unroll
            for (int mt = 0; mt < 4; mt++) {
                int r = warp_m * 64 + mt * 16 + (lane & 15);
                ldm_x4(a[mt][0], a[mt][1], a[mt][2], a[mt][3],
                       sA + swz128((uint32_t)(r * 128) + kOff));
            }
            uint32_t b[4][2];
#pragma unroll
            for (int p = 0; p < 2; p++) {             // 2 n-tile pairs
                int r = warp_n * 32 + p * 16 + (lane & 15);
                uint32_t t0, t1, t2, t3;
                ldm_x4(t0, t1, t2, t3, sB + swz128((uint32_t)(r * 128) + kOff));
                b[2 * p][0] = t0;  b[2 * p][1] = t2;     // n rows 0-7 of pair
                b[2 * p + 1][0] = t1;  b[2 * p + 1][1] = t3; // n rows 8-15
            }
#pragma unroll
            for (int mt = 0; mt < 4; mt++)
#pragma unroll
                for (int nt = 0; nt < 4; nt++)
                    mma16816(acc[mt][nt], a[mt], b[nt]);
        }
        __syncthreads();
    }

    // Epilogue: fragment -> fp32 g_h
    const int g = lane >> 2, tig = lane & 3;
#pragma unroll
    for (int mt = 0; mt < 4; mt++) {
        const int row0 = rowBase + warp_m * 64 + mt * 16 + g;
#pragma unroll
        for (int nt = 0; nt < 4; nt++) {
            const int col = colBase + warp_n * 32 + nt * 8 + 2 * tig;
            if (row0 < NN)
                *(float2*)&g_h[(size_t)row0 * 512 + col] =
                    make_float2(acc[mt][nt][0], acc[mt][nt][1]);
            if (row0 + 8 < NN)
                *(float2*)&g_h[(size_t)(row0 + 8) * 512 + col] =
                    make_float2(acc[mt][nt][2], acc[mt][nt][3]);
        }
    }
}

// ---------------------------------------------------------------------------
// Aggregation: acc = dinv_i^2*h_i + b + sum dinv_i*dinv_s*h_s
// TO_A2: write relu-split bf16 into g_A2 (feeds next GEMM)
// else:  write fp32 g_pre (feeds classifier)
// ---------------------------------------------------------------------------
template <bool TO_A2>
__global__ __launch_bounds__(128)
void aggregate_kernel(const float* __restrict__ bias) {
    const float* __restrict__ h = g_h;
    const int i = blockIdx.x;
    const int f = threadIdx.x * 4;
    const float di = g_dinv[i];

    float4 hv = *reinterpret_cast<const float4*>(&h[(size_t)i * 512 + f]);
    float4 bv = *reinterpret_cast<const float4*>(&bias[f]);
    const float w0 = di * di;
    float4 acc;
    acc.x = fmaf(w0, hv.x, bv.x);
    acc.y = fmaf(w0, hv.y, bv.y);
    acc.z = fmaf(w0, hv.z, bv.z);
    acc.w = fmaf(w0, hv.w, bv.w);

    const int s0 = g_rowptr[i];
    const int s1 = g_rowptr[i + 1];
    for (int e = s0; e < s1; e++) {
        int s = g_col[e];
        float w = di * g_dinv[s];
        float4 v = *reinterpret_cast<const float4*>(&h[(size_t)s * 512 + f]);
        acc.x = fmaf(w, v.x, acc.x);
        acc.y = fmaf(w, v.y, acc.y);
        acc.z = fmaf(w, v.z, acc.z);
        acc.w = fmaf(w, v.w, acc.w);
    }

    if (!TO_A2) {
        *reinterpret_cast<float4*>(&g_pre[(size_t)i * 512 + f]) = acc;
    } else {
        float r0 = fmaxf(acc.x, 0.f), r1 = fmaxf(acc.y, 0.f);
        float r2 = fmaxf(acc.z, 0.f), r3 = fmaxf(acc.w, 0.f);
        __nv_bfloat162 hh0, ll0, hh1, ll1;
        split2(r0, r1, hh0, ll0);
        split2(r2, r3, hh1, ll1);
        size_t b = (size_t)i * KE2 + (f >> 1);
        g_A2[b]       = hh0;  g_A2[b + 1]   = hh1;
        g_A2[b + 256] = ll0;  g_A2[b + 257] = ll1;
        g_A2[b + 512] = hh0;  g_A2[b + 513] = hh1;
    }
}

// ---------------------------------------------------------------------------
// Final: out[N,16] = relu(g_pre) @ Wl + bl. Wl staged in smem; warp per row.
// ---------------------------------------------------------------------------
__global__ __launch_bounds__(256)
void final_kernel(const float* __restrict__ Wl, const float* __restrict__ bl,
                  float* __restrict__ out) {
    __shared__ __align__(16) float WlS[512 * 16];
    __shared__ float outS[8][16];
    const float* __restrict__ pre = g_pre;

    const int tid = threadIdx.x;
    for (int idx = tid; idx < 512 * 16 / 4; idx += 256)
        reinterpret_cast<float4*>(WlS)[idx] =
            reinterpret_cast<const float4*>(Wl)[idx];
    __syncthreads();

    const int w = tid >> 5;
    const int lane = tid & 31;
    const int row = blockIdx.x * 8 + w;
    if (row < NN) {
        float4 acc0 = make_float4(0.f, 0.f, 0.f, 0.f);
        float4 acc1 = acc0, acc2 = acc0, acc3 = acc0;
#pragma unroll
        for (int kk = 0; kk < 16; kk++) {
            int k = kk * 32 + lane;
            float a = fmaxf(pre[(size_t)row * 512 + k], 0.f);
            const float4* wrow = reinterpret_cast<const float4*>(&WlS[k * 16]);
            float4 w0 = wrow[0], w1 = wrow[1], w2 = wrow[2], w3 = wrow[3];
            acc0.x = fmaf(a, w0.x, acc0.x); acc0.y = fmaf(a, w0.y, acc0.y);
            acc0.z = fmaf(a, w0.z, acc0.z); acc0.w = fmaf(a, w0.w, acc0.w);
            acc1.x = fmaf(a, w1.x, acc1.x); acc1.y = fmaf(a, w1.y, acc1.y);
            acc1.z = fmaf(a, w1.z, acc1.z); acc1.w = fmaf(a, w1.w, acc1.w);
            acc2.x = fmaf(a, w2.x, acc2.x); acc2.y = fmaf(a, w2.y, acc2.y);
            acc2.z = fmaf(a, w2.z, acc2.z); acc2.w = fmaf(a, w2.w, acc2.w);
            acc3.x = fmaf(a, w3.x, acc3.x); acc3.y = fmaf(a, w3.y, acc3.y);
            acc3.z = fmaf(a, w3.z, acc3.z); acc3.w = fmaf(a, w3.w, acc3.w);
        }
#pragma unroll
        for (int off = 16; off > 0; off >>= 1) {
            acc0.x += __shfl_xor_sync(0xffffffff, acc0.x, off);
            acc0.y += __shfl_xor_sync(0xffffffff, acc0.y, off);
            acc0.z += __shfl_xor_sync(0xffffffff, acc0.z, off);
            acc0.w += __shfl_xor_sync(0xffffffff, acc0.w, off);
            acc1.x += __shfl_xor_sync(0xffffffff, acc1.x, off);
            acc1.y += __shfl_xor_sync(0xffffffff, acc1.y, off);
            acc1.z += __shfl_xor_sync(0xffffffff, acc1.z, off);
            acc1.w += __shfl_xor_sync(0xffffffff, acc1.w, off);
            acc2.x += __shfl_xor_sync(0xffffffff, acc2.x, off);
            acc2.y += __shfl_xor_sync(0xffffffff, acc2.y, off);
            acc2.z += __shfl_xor_sync(0xffffffff, acc2.z, off);
            acc2.w += __shfl_xor_sync(0xffffffff, acc2.w, off);
            acc3.x += __shfl_xor_sync(0xffffffff, acc3.x, off);
            acc3.y += __shfl_xor_sync(0xffffffff, acc3.y, off);
            acc3.z += __shfl_xor_sync(0xffffffff, acc3.z, off);
            acc3.w += __shfl_xor_sync(0xffffffff, acc3.w, off);
        }
        if (lane == 0) {
            *reinterpret_cast<float4*>(&outS[w][0])  = acc0;
            *reinterpret_cast<float4*>(&outS[w][4])  = acc1;
            *reinterpret_cast<float4*>(&outS[w][8])  = acc2;
            *reinterpret_cast<float4*>(&outS[w][12]) = acc3;
        }
        __syncwarp();
        if (lane < 16)
            out[(size_t)row * 16 + lane] = outS[w][lane] + bl[lane];
    }
}

// ---------------------------------------------------------------------------
// Launch — pure kernel launches, no runtime API calls
// ---------------------------------------------------------------------------
extern "C" void kernel_launch(void* const* d_in, const int* in_sizes, int n_in,
                              void* d_out, int out_size) {
    const float* x  = (const float*)d_in[0];
    const void*  ei = d_in[1];
    const float* W1 = (const float*)d_in[2];
    const float* b1 = (const float*)d_in[3];
    const float* W2 = (const float*)d_in[4];
    const float* b2 = (const float*)d_in[5];
    const float* Wl = (const float*)d_in[6];
    const float* bl = (const float*)d_in[7];
    float* out = (float*)d_out;

    // CSR build + degrees
    detect_kernel<<<1, 256>>>((const int*)ei);
    init_counts_kernel<<<(NN + 255) / 256, 256>>>();
    decode_count_kernel<<<(EE + 255) / 256, 256>>>(ei);
    scan_kernel<<<1, 1024>>>();
    dinv_kernel<<<(NN + 255) / 256, 256>>>();
    fill_edges_kernel<<<(EE + 255) / 256, 256>>>();

    // bf16 split operand prep
    convx_kernel<<<MPAD, 256>>>(x);
    convw_kernel<1><<<512, 256>>>(W1);
    convw_kernel<2><<<512, 256>>>(W2);

    dim3 gemmGrid(MPAD / 128, 4);   // (80, 4)

    // Layer 1
    gemm_mma_kernel<1><<<gemmGrid, 256>>>();
    aggregate_kernel<true><<<NN, 128>>>(b1);     // relu+split -> g_A2
    // Layer 2
    gemm_mma_kernel<2><<<gemmGrid, 256>>>();
    aggregate_kernel<false><<<NN, 128>>>(b2);    // fp32 -> g_pre
    // Classifier
    final_kernel<<<(NN + 7) / 8, 256>>>(Wl, bl, out);
}

// round 15
// speedup vs baseline: 1.2092x; 1.0731x over previous
#include <cuda_runtime.h>
#include <cuda_bf16.h>
#include <cstdint>

// Problem constants (fixed by the reference)
#define NN   10000
#define EE   160000
#define MPAD 10240            // 80 * 128 rows (padded M)
#define KE   1536             // extended K: [hi | lo | hi] * 512
#define KE2  768              // KE in bf16x2 units

#define STAGES      3
#define STAGE_BYTES 32768     // A 16KB + B 16KB per stage
#define GEMM_DSMEM  (STAGES * STAGE_BYTES)

// ---------------------------------------------------------------------------
// Scratch (__device__ globals; no allocations, no cudaGetSymbolAddress)
// ---------------------------------------------------------------------------
__device__ float g_h[NN * 512];        // GEMM output (fp32)
__device__ float g_pre[NN * 512];      // layer-2 aggregated pre-activation
__device__ float g_dinv[NN];
__device__ int   g_count[NN];
__device__ int   g_cursor[NN];
__device__ int   g_rowptr[NN + 1];
__device__ int   g_col[EE];
__device__ int   g_src[EE];
__device__ int   g_dst[EE];
__device__ int   g_is64;
// bf16 split operands. A pattern along K: [hiA | loA | hiA]
// B pattern along K: [hiB | hiB | loB]  =>  sum = hi*hi + lo*hi + hi*lo
__device__ __align__(16) __nv_bfloat162 g_A2[(size_t)MPAD * KE2];   // ~31.5 MB
__device__ __align__(16) __nv_bfloat162 g_B1[(size_t)512 * KE2];
__device__ __align__(16) __nv_bfloat162 g_B2[(size_t)512 * KE2];

// ---------------------------------------------------------------------------
// Warp-MMA helpers (baseline PTX only: ldmatrix sm_75+, mma.sync bf16 sm_80+,
// cp.async sm_80+ — nothing sm_103a-gated; harness emits compute_103).
// ---------------------------------------------------------------------------
__device__ __forceinline__ uint32_t smem_u32(const void* p) {
    uint32_t a;
    asm("{ .reg .u64 t; cvta.to.shared.u64 t, %1; cvt.u32.u64 %0, t; }"
        : "=r"(a) : "l"(p));
    return a;
}
__device__ __forceinline__ void ldm_x4(uint32_t& r0, uint32_t& r1,
                                       uint32_t& r2, uint32_t& r3, uint32_t a) {
    asm volatile("ldmatrix.sync.aligned.m8n8.x4.shared.b16 {%0,%1,%2,%3}, [%4];"
                 : "=r"(r0), "=r"(r1), "=r"(r2), "=r"(r3) : "r"(a));
}
__device__ __forceinline__ void mma16816(float* c, const uint32_t* a,
                                         const uint32_t* b) {
    asm volatile(
        "mma.sync.aligned.m16n8k16.row.col.f32.bf16.bf16.f32 "
        "{%0,%1,%2,%3}, {%4,%5,%6,%7}, {%8,%9}, {%0,%1,%2,%3};"
        : "+f"(c[0]), "+f"(c[1]), "+f"(c[2]), "+f"(c[3])
        : "r"(a[0]), "r"(a[1]), "r"(a[2]), "r"(a[3]), "r"(b[0]), "r"(b[1]));
}
__device__ __forceinline__ uint32_t swz128(uint32_t off) {
    return off ^ ((off >> 3) & 0x70);
}
__device__ __forceinline__ void cp16(uint32_t dst, const void* src) {
    asm volatile("cp.async.cg.shared.global [%0], [%1], 16;"
                 :: "r"(dst), "l"(src));
}
__device__ __forceinline__ void cp_commit() {
    asm volatile("cp.async.commit_group;");
}
template <int N>
__device__ __forceinline__ void cp_wait() {
    asm volatile("cp.async.wait_group %0;" :: "n"(N));
}

// ---------------------------------------------------------------------------
// Edge-index dtype detection (int64 vs silently-int32 from JAX x64-off)
// ---------------------------------------------------------------------------
__global__ void detect_kernel(const int* __restrict__ w) {
    __shared__ int nz;
    if (threadIdx.x == 0) nz = 0;
    __syncthreads();
    if (w[2 * threadIdx.x + 1] != 0) atomicOr(&nz, 1);
    __syncthreads();
    if (threadIdx.x == 0) g_is64 = (nz == 0) ? 1 : 0;
}

// ---------------------------------------------------------------------------
// CSR build
// ---------------------------------------------------------------------------
__global__ void init_counts_kernel() {
    int i = blockIdx.x * blockDim.x + threadIdx.x;
    if (i < NN) { g_count[i] = 0; g_cursor[i] = 0; }
}

__global__ void decode_count_kernel(const void* __restrict__ ei) {
    int e = blockIdx.x * blockDim.x + threadIdx.x;
    if (e < EE) {
        int src, dst;
        if (g_is64) {
            const long long* p = (const long long*)ei;
            src = (int)p[e];  dst = (int)p[EE + e];
        } else {
            const int* p = (const int*)ei;
            src = p[e];  dst = p[EE + e];
        }
        src = min(max(src, 0), NN - 1);
        dst = min(max(dst, 0), NN - 1);
        g_src[e] = src;  g_dst[e] = dst;
        atomicAdd(&g_count[dst], 1);
    }
}

// warp-shuffle based exclusive scan
__global__ void scan_kernel() {
    __shared__ int wsum[32];
    const int t = threadIdx.x, lane = t & 31, wid = t >> 5;
    const int base = t * 10;
    int c[10], s = 0;
#pragma unroll
    for (int i = 0; i < 10; i++) {
        int idx = base + i;
        c[i] = (idx < NN) ? g_count[idx] : 0;
        s += c[i];
    }
    int incl = s;
#pragma unroll
    for (int off = 1; off < 32; off <<= 1) {
        int v = __shfl_up_sync(0xffffffffu, incl, off);
        if (lane >= off) incl += v;
    }
    if (lane == 31) wsum[wid] = incl;
    __syncthreads();
    if (wid == 0) {
        int w = wsum[lane];
#pragma unroll
        for (int off = 1; off < 32; off <<= 1) {
            int v = __shfl_up_sync(0xffffffffu, w, off);
            if (lane >= off) w += v;
        }
        wsum[lane] = w;
    }
    __syncthreads();
    int off = (wid ? wsum[wid - 1] : 0) + incl - s;
#pragma unroll
    for (int i = 0; i < 10; i++) {
        int idx = base + i;
        if (idx < NN) { g_rowptr[idx] = off; off += c[i]; }
    }
    if (t == 1023) g_rowptr[NN] = off;
}

__global__ void dinv_kernel() {
    int i = blockIdx.x * blockDim.x + threadIdx.x;
    if (i < NN) g_dinv[i] = rsqrtf((float)g_count[i] + 1.0f);
}

__global__ void fill_edges_kernel() {
    int e = blockIdx.x * blockDim.x + threadIdx.x;
    if (e < EE) {
        int dst = g_dst[e];
        int pos = atomicAdd(&g_cursor[dst], 1);
        g_col[g_rowptr[dst] + pos] = g_src[e];
    }
}

// ---------------------------------------------------------------------------
// Conversions: fp32 -> bf16 hi/lo split, laid out along extended K
// ---------------------------------------------------------------------------
__device__ __forceinline__ void split2(float a0, float a1,
                                       __nv_bfloat162& hh, __nv_bfloat162& ll) {
    __nv_bfloat16 h0 = __float2bfloat16(a0), h1 = __float2bfloat16(a1);
    __nv_bfloat16 l0 = __float2bfloat16(a0 - __bfloat162float(h0));
    __nv_bfloat16 l1 = __float2bfloat16(a1 - __bfloat162float(h1));
    hh = __halves2bfloat162(h0, h1);
    ll = __halves2bfloat162(l0, l1);
}

// x[10000,512] -> g_A2 rows [0,10240): pattern [hi | lo | hi], pad rows = 0
__global__ void convx_kernel(const float* __restrict__ x) {
    int i = blockIdx.x * 256 + threadIdx.x;       // pair index
    int row = i >> 8, cp = i & 255;
    float a0 = 0.f, a1 = 0.f;
    if (row < NN) {
        float2 v = ((const float2*)x)[(size_t)row * 256 + cp];
        a0 = v.x; a1 = v.y;
    }
    __nv_bfloat162 hh, ll;
    split2(a0, a1, hh, ll);
    size_t b = (size_t)row * KE2 + cp;
    g_A2[b] = hh; g_A2[b + 256] = ll; g_A2[b + 512] = hh;
}

// W[512,512] (k-major rows) -> Bsel[n][k] transposed split: [hi | hi | lo]
template <int WHICH>   // 1 -> g_B1, 2 -> g_B2
__global__ void convw_kernel(const float* __restrict__ W) {
    __nv_bfloat162* out = (WHICH == 1) ? g_B1 : g_B2;
    int i = blockIdx.x * 256 + threadIdx.x;       // (n, kp)
    int n = i >> 8, kp = i & 255;
    float a0 = W[(size_t)(2 * kp) * 512 + n];
    float a1 = W[(size_t)(2 * kp + 1) * 512 + n];
    __nv_bfloat162 hh, ll;
    split2(a0, a1, hh, ll);
    size_t b = (size_t)n * KE2 + kp;
    out[b] = hh; out[b + 256] = hh; out[b + 512] = ll;
}

// ---------------------------------------------------------------------------
// Warp-MMA GEMM, cp.async 3-stage pipeline:
// g_h[M,512] = A2 @ B^T over extended K=1536 (bf16 split)
// CTA: 128x128 tile, 256 threads / 8 warps, warp tile 64x32 (4x4 m16n8k16).
// 24 K-chunks of 64 bf16; stage = 32KB SW128-swizzled (A 16KB | B 16KB).
// ---------------------------------------------------------------------------
template <int WHICH>   // weight select: 1 -> g_B1, 2 -> g_B2
__global__ __launch_bounds__(256, 2)
void gemm_mma_kernel() {
    extern __shared__ __align__(1024) char sm[];
    const __nv_bfloat162* __restrict__ Bsel = (WHICH == 1) ? g_B1 : g_B2;

    const int tid = threadIdx.x;
    const int lane = tid & 31, wid = tid >> 5;
    const int warp_m = wid & 1;       // 2 m-blocks of 64
    const int warp_n = wid >> 1;      // 4 n-blocks of 32
    const int rowBase = blockIdx.x * 128;
    const int colBase = blockIdx.y * 128;

    // Cooperative load mapping: threads 0-127 -> A rows, 128-255 -> B rows.
    const int half = tid >> 7;
    const int lrow = tid & 127;
    const uint4* __restrict__ gsrc = half
        ? (const uint4*)(Bsel + (size_t)(colBase + lrow) * KE2)
        : (const uint4*)(g_A2 + (size_t)(rowBase + lrow) * KE2);

    const uint32_t smBase = smem_u32(sm);
    // per-thread swizzled destination offsets within a stage
    const uint32_t dstHalf = half * 16384u;

    // issue cp.async group for chunk c into stage c % STAGES
    auto issue = [&](int c) {
        uint32_t stage = smBase + (uint32_t)(c % STAGES) * STAGE_BYTES + dstHalf;
        const uint4* src = gsrc + c * 8;
#pragma unroll
        for (int j = 0; j < 8; j++)
            cp16(stage + swz128((uint32_t)(lrow * 128 + j * 16)), src + j);
        cp_commit();
    };

    float acc[4][4][4];
#pragma unroll
    for (int i = 0; i < 4; i++)
#pragma unroll
        for (int j = 0; j < 4; j++)
#pragma unroll
            for (int r = 0; r < 4; r++) acc[i][j][r] = 0.f;

    issue(0); issue(1);               // prologue: STAGES-1 groups in flight

    for (int c = 0; c < 24; c++) {
        if (c + STAGES - 1 < 24) cp_wait<STAGES - 2>();
        else                     cp_wait<0>();
        __syncthreads();
        if (c + STAGES - 1 < 24) issue(c + STAGES - 1);

        const uint32_t sA = smBase + (uint32_t)(c % STAGES) * STAGE_BYTES;
        const uint32_t sB = sA + 16384u;

#pragma unroll
        for (int ks = 0; ks < 4; ks++) {              // 4 x K=16
            const uint32_t kOff = ks * 32 + ((lane >> 4) * 16);
            uint32_t a[4][4];
#pragma unroll
            for (int mt = 0; mt < 4; mt++) {
                int r = warp_m * 64 + mt * 16 + (lane & 15);
                ldm_x4(a[mt][0], a[mt][1], a[mt][2], a[mt][3],
                       sA + swz128((uint32_t)(r * 128) + kOff));
            }
            uint32_t b[4][2];
#pragma unroll
            for (int p = 0; p < 2; p++) {             // 2 n-tile pairs
                int r = warp_n * 32 + p * 16 + (lane & 15);
                uint32_t t0, t1, t2, t3;
                ldm_x4(t0, t1, t2, t3, sB + swz128((uint32_t)(r * 128) + kOff));
                b[2 * p][0] = t0;      b[2 * p][1] = t2;
                b[2 * p + 1][0] = t1;  b[2 * p + 1][1] = t3;
            }
#pragma unroll
            for (int mt = 0; mt < 4; mt++)
#pragma unroll
                for (int nt = 0; nt < 4; nt++)
                    mma16816(acc[mt][nt], a[mt], b[nt]);
        }
        __syncthreads();
    }

    // Epilogue: fragment -> fp32 g_h
    const int g = lane >> 2, tig = lane & 3;
#pragma unroll
    for (int mt = 0; mt < 4; mt++) {
        const int row0 = rowBase + warp_m * 64 + mt * 16 + g;
#pragma unroll
        for (int nt = 0; nt < 4; nt++) {
            const int col = colBase + warp_n * 32 + nt * 8 + 2 * tig;
            if (row0 < NN)
                *(float2*)&g_h[(size_t)row0 * 512 + col] =
                    make_float2(acc[mt][nt][0], acc[mt][nt][1]);
            if (row0 + 8 < NN)
                *(float2*)&g_h[(size_t)(row0 + 8) * 512 + col] =
                    make_float2(acc[mt][nt][2], acc[mt][nt][3]);
        }
    }
}

// ---------------------------------------------------------------------------
// Aggregation: acc = dinv_i^2*h_i + b + sum dinv_i*dinv_s*h_s
// TO_A2: write relu-split bf16 into g_A2 (feeds next GEMM)
// else:  write fp32 g_pre (feeds classifier)
// ---------------------------------------------------------------------------
template <bool TO_A2>
__global__ __launch_bounds__(128)
void aggregate_kernel(const float* __restrict__ bias) {
    const float* __restrict__ h = g_h;
    const int i = blockIdx.x;
    const int f = threadIdx.x * 4;
    const float di = g_dinv[i];

    float4 hv = *reinterpret_cast<const float4*>(&h[(size_t)i * 512 + f]);
    float4 bv = *reinterpret_cast<const float4*>(&bias[f]);
    const float w0 = di * di;
    float4 acc;
    acc.x = fmaf(w0, hv.x, bv.x);
    acc.y = fmaf(w0, hv.y, bv.y);
    acc.z = fmaf(w0, hv.z, bv.z);
    acc.w = fmaf(w0, hv.w, bv.w);

    const int s0 = g_rowptr[i];
    const int s1 = g_rowptr[i + 1];
    for (int e = s0; e < s1; e++) {
        int s = g_col[e];
        float w = di * g_dinv[s];
        float4 v = *reinterpret_cast<const float4*>(&h[(size_t)s * 512 + f]);
        acc.x = fmaf(w, v.x, acc.x);
        acc.y = fmaf(w, v.y, acc.y);
        acc.z = fmaf(w, v.z, acc.z);
        acc.w = fmaf(w, v.w, acc.w);
    }

    if (!TO_A2) {
        *reinterpret_cast<float4*>(&g_pre[(size_t)i * 512 + f]) = acc;
    } else {
        float r0 = fmaxf(acc.x, 0.f), r1 = fmaxf(acc.y, 0.f);
        float r2 = fmaxf(acc.z, 0.f), r3 = fmaxf(acc.w, 0.f);
        __nv_bfloat162 hh0, ll0, hh1, ll1;
        split2(r0, r1, hh0, ll0);
        split2(r2, r3, hh1, ll1);
        size_t b = (size_t)i * KE2 + (f >> 1);
        g_A2[b]       = hh0;  g_A2[b + 1]   = hh1;
        g_A2[b + 256] = ll0;  g_A2[b + 257] = ll1;
        g_A2[b + 512] = hh0;  g_A2[b + 513] = hh1;
    }
}

// ---------------------------------------------------------------------------
// Final: out[N,16] = relu(g_pre) @ Wl + bl. Wl staged in smem; warp per row.
// ---------------------------------------------------------------------------
__global__ __launch_bounds__(256)
void final_kernel(const float* __restrict__ Wl, const float* __restrict__ bl,
                  float* __restrict__ out) {
    __shared__ __align__(16) float WlS[512 * 16];
    __shared__ float outS[8][16];
    const float* __restrict__ pre = g_pre;

    const int tid = threadIdx.x;
    for (int idx = tid; idx < 512 * 16 / 4; idx += 256)
        reinterpret_cast<float4*>(WlS)[idx] =
            reinterpret_cast<const float4*>(Wl)[idx];
    __syncthreads();

    const int w = tid >> 5;
    const int lane = tid & 31;
    const int row = blockIdx.x * 8 + w;
    if (row < NN) {
        float4 acc0 = make_float4(0.f, 0.f, 0.f, 0.f);
        float4 acc1 = acc0, acc2 = acc0, acc3 = acc0;
#pragma unroll
        for (int kk = 0; kk < 16; kk++) {
            int k = kk * 32 + lane;
            float a = fmaxf(pre[(size_t)row * 512 + k], 0.f);
            const float4* wrow = reinterpret_cast<const float4*>(&WlS[k * 16]);
            float4 w0 = wrow[0], w1 = wrow[1], w2 = wrow[2], w3 = wrow[3];
            acc0.x = fmaf(a, w0.x, acc0.x); acc0.y = fmaf(a, w0.y, acc0.y);
            acc0.z = fmaf(a, w0.z, acc0.z); acc0.w = fmaf(a, w0.w, acc0.w);
            acc1.x = fmaf(a, w1.x, acc1.x); acc1.y = fmaf(a, w1.y, acc1.y);
            acc1.z = fmaf(a, w1.z, acc1.z); acc1.w = fmaf(a, w1.w, acc1.w);
            acc2.x = fmaf(a, w2.x, acc2.x); acc2.y = fmaf(a, w2.y, acc2.y);
            acc2.z = fmaf(a, w2.z, acc2.z); acc2.w = fmaf(a, w2.w, acc2.w);
            acc3.x = fmaf(a, w3.x, acc3.x); acc3.y = fmaf(a, w3.y, acc3.y);
            acc3.z = fmaf(a, w3.z, acc3.z); acc3.w = fmaf(a, w3.w, acc3.w);
        }
#pragma unroll
        for (int off = 16; off > 0; off >>= 1) {
            acc0.x += __shfl_xor_sync(0xffffffff, acc0.x, off);
            acc0.y += __shfl_xor_sync(0xffffffff, acc0.y, off);
            acc0.z += __shfl_xor_sync(0xffffffff, acc0.z, off);
            acc0.w += __shfl_xor_sync(0xffffffff, acc0.w, off);
            acc1.x += __shfl_xor_sync(0xffffffff, acc1.x, off);
            acc1.y += __shfl_xor_sync(0xffffffff, acc1.y, off);
            acc1.z += __shfl_xor_sync(0xffffffff, acc1.z, off);
            acc1.w += __shfl_xor_sync(0xffffffff, acc1.w, off);
            acc2.x += __shfl_xor_sync(0xffffffff, acc2.x, off);
            acc2.y += __shfl_xor_sync(0xffffffff, acc2.y, off);
            acc2.z += __shfl_xor_sync(0xffffffff, acc2.z, off);
            acc2.w += __shfl_xor_sync(0xffffffff, acc2.w, off);
            acc3.x += __shfl_xor_sync(0xffffffff, acc3.x, off);
            acc3.y += __shfl_xor_sync(0xffffffff, acc3.y, off);
            acc3.z += __shfl_xor_sync(0xffffffff, acc3.z, off);
            acc3.w += __shfl_xor_sync(0xffffffff, acc3.w, off);
        }
        if (lane == 0) {
            *reinterpret_cast<float4*>(&outS[w][0])  = acc0;
            *reinterpret_cast<float4*>(&outS[w][4])  = acc1;
            *reinterpret_cast<float4*>(&outS[w][8])  = acc2;
            *reinterpret_cast<float4*>(&outS[w][12]) = acc3;
        }
        __syncwarp();
        if (lane < 16)
            out[(size_t)row * 16 + lane] = outS[w][lane] + bl[lane];
    }
}

// ---------------------------------------------------------------------------
// Launch — kernel launches + one idempotent attribute set (not a stream op)
// ---------------------------------------------------------------------------
extern "C" void kernel_launch(void* const* d_in, const int* in_sizes, int n_in,
                              void* d_out, int out_size) {
    const float* x  = (const float*)d_in[0];
    const void*  ei = d_in[1];
    const float* W1 = (const float*)d_in[2];
    const float* b1 = (const float*)d_in[3];
    const float* W2 = (const float*)d_in[4];
    const float* b2 = (const float*)d_in[5];
    const float* Wl = (const float*)d_in[6];
    const float* bl = (const float*)d_in[7];
    float* out = (float*)d_out;

    // opt-in to 96KB dynamic smem for the pipelined GEMMs (device-global
    // state, not a stream operation — safe under graph capture)
    cudaFuncSetAttribute(gemm_mma_kernel<1>,
                         cudaFuncAttributeMaxDynamicSharedMemorySize, GEMM_DSMEM);
    cudaFuncSetAttribute(gemm_mma_kernel<2>,
                         cudaFuncAttributeMaxDynamicSharedMemorySize, GEMM_DSMEM);

    // CSR build + degrees
    detect_kernel<<<1, 256>>>((const int*)ei);
    init_counts_kernel<<<(NN + 255) / 256, 256>>>();
    decode_count_kernel<<<(EE + 255) / 256, 256>>>(ei);
    scan_kernel<<<1, 1024>>>();
    dinv_kernel<<<(NN + 255) / 256, 256>>>();
    fill_edges_kernel<<<(EE + 255) / 256, 256>>>();

    // bf16 split operand prep
    convx_kernel<<<MPAD, 256>>>(x);
    convw_kernel<1><<<512, 256>>>(W1);
    convw_kernel<2><<<512, 256>>>(W2);

    dim3 gemmGrid(MPAD / 128, 4);   // (80, 4)

    // Layer 1
    gemm_mma_kernel<1><<<gemmGrid, 256, GEMM_DSMEM>>>();
    aggregate_kernel<true><<<NN, 128>>>(b1);     // relu+split -> g_A2
    // Layer 2
    gemm_mma_kernel<2><<<gemmGrid, 256, GEMM_DSMEM>>>();
    aggregate_kernel<false><<<NN, 128>>>(b2);    // fp32 -> g_pre
    // Classifier
    final_kernel<<<(NN + 7) / 8, 256>>>(Wl, bl, out);
}

// round 16
// speedup vs baseline: 1.5612x; 1.2911x over previous
#include <cuda_runtime.h>
#include <cuda_fp16.h>
#include <cstdint>

// Problem constants (fixed by the reference)
#define NN   10000
#define EE   160000
#define MPAD 10240            // 80 * 128 rows (padded M)
#define KE   1024             // extended K: [hi | lo] * 512 (fp16 2-term split)
#define KE2  512              // KE in half2 units
#define NCHUNK 16             // K-chunks of 64 halves

#define STAGES      3
#define STAGE_BYTES 32768     // A 16KB + B 16KB per stage
#define GEMM_DSMEM  (STAGES * STAGE_BYTES)

// ---------------------------------------------------------------------------
// Scratch (__device__ globals; no allocations, no cudaGetSymbolAddress)
// ---------------------------------------------------------------------------
__device__ float g_h[NN * 512];        // GEMM output (fp32)
__device__ float g_pre[NN * 512];      // layer-2 aggregated pre-activation
__device__ float g_dinv[NN];
__device__ int   g_count[NN];
__device__ int   g_cursor[NN];
__device__ int   g_rowptr[NN + 1];
__device__ int   g_col[EE];
__device__ int   g_src[EE];
__device__ int   g_dst[EE];
__device__ int   g_is64;
// fp16 split operands. A pattern along K: [hiA | loA]
// B pattern along K: [hiB | hiB]  =>  sum = hiA*hiB + loA*hiB = A*hiB
// (missing A*loB ~ 2^-11.7 rel — calibrated ~3e-4 final, threshold 1e-3)
__device__ __align__(16) __half2 g_A2[(size_t)MPAD * KE2];   // ~21 MB
__device__ __align__(16) __half2 g_B1[(size_t)512 * KE2];    // 1 MB
__device__ __align__(16) __half2 g_B2[(size_t)512 * KE2];

// ---------------------------------------------------------------------------
// Warp-MMA helpers (baseline PTX only: ldmatrix sm_75+, mma.sync f16 sm_80+,
// cp.async sm_80+ — nothing sm_103a-gated; harness emits compute_103).
// ---------------------------------------------------------------------------
__device__ __forceinline__ uint32_t smem_u32(const void* p) {
    uint32_t a;
    asm("{ .reg .u64 t; cvta.to.shared.u64 t, %1; cvt.u32.u64 %0, t; }"
        : "=r"(a) : "l"(p));
    return a;
}
__device__ __forceinline__ void ldm_x4(uint32_t& r0, uint32_t& r1,
                                       uint32_t& r2, uint32_t& r3, uint32_t a) {
    asm volatile("ldmatrix.sync.aligned.m8n8.x4.shared.b16 {%0,%1,%2,%3}, [%4];"
                 : "=r"(r0), "=r"(r1), "=r"(r2), "=r"(r3) : "r"(a));
}
__device__ __forceinline__ void mma16816(float* c, const uint32_t* a,
                                         const uint32_t* b) {
    asm volatile(
        "mma.sync.aligned.m16n8k16.row.col.f32.f16.f16.f32 "
        "{%0,%1,%2,%3}, {%4,%5,%6,%7}, {%8,%9}, {%0,%1,%2,%3};"
        : "+f"(c[0]), "+f"(c[1]), "+f"(c[2]), "+f"(c[3])
        : "r"(a[0]), "r"(a[1]), "r"(a[2]), "r"(a[3]), "r"(b[0]), "r"(b[1]));
}
__device__ __forceinline__ uint32_t swz128(uint32_t off) {
    return off ^ ((off >> 3) & 0x70);
}
__device__ __forceinline__ void cp16(uint32_t dst, const void* src) {
    asm volatile("cp.async.cg.shared.global [%0], [%1], 16;"
                 :: "r"(dst), "l"(src));
}
__device__ __forceinline__ void cp_commit() {
    asm volatile("cp.async.commit_group;");
}
template <int N>
__device__ __forceinline__ void cp_wait() {
    asm volatile("cp.async.wait_group %0;" :: "n"(N));
}

// ---------------------------------------------------------------------------
// Edge-index dtype detection (int64 vs silently-int32 from JAX x64-off)
// ---------------------------------------------------------------------------
__global__ void detect_kernel(const int* __restrict__ w) {
    __shared__ int nz;
    if (threadIdx.x == 0) nz = 0;
    __syncthreads();
    if (w[2 * threadIdx.x + 1] != 0) atomicOr(&nz, 1);
    __syncthreads();
    if (threadIdx.x == 0) g_is64 = (nz == 0) ? 1 : 0;
}

// ---------------------------------------------------------------------------
// CSR build
// ---------------------------------------------------------------------------
__global__ void init_counts_kernel() {
    int i = blockIdx.x * blockDim.x + threadIdx.x;
    if (i < NN) { g_count[i] = 0; g_cursor[i] = 0; }
}

__global__ void decode_count_kernel(const void* __restrict__ ei) {
    int e = blockIdx.x * blockDim.x + threadIdx.x;
    if (e < EE) {
        int src, dst;
        if (g_is64) {
            const long long* p = (const long long*)ei;
            src = (int)p[e];  dst = (int)p[EE + e];
        } else {
            const int* p = (const int*)ei;
            src = p[e];  dst = p[EE + e];
        }
        src = min(max(src, 0), NN - 1);
        dst = min(max(dst, 0), NN - 1);
        g_src[e] = src;  g_dst[e] = dst;
        atomicAdd(&g_count[dst], 1);
    }
}

// warp-shuffle exclusive scan; also emits dinv (fused, saves a launch)
__global__ void scan_kernel() {
    __shared__ int wsum[32];
    const int t = threadIdx.x, lane = t & 31, wid = t >> 5;
    const int base = t * 10;
    int c[10], s = 0;
#pragma unroll
    for (int i = 0; i < 10; i++) {
        int idx = base + i;
        c[i] = (idx < NN) ? g_count[idx] : 0;
        s += c[i];
    }
    int incl = s;
#pragma unroll
    for (int off = 1; off < 32; off <<= 1) {
        int v = __shfl_up_sync(0xffffffffu, incl, off);
        if (lane >= off) incl += v;
    }
    if (lane == 31) wsum[wid] = incl;
    __syncthreads();
    if (wid == 0) {
        int w = wsum[lane];
#pragma unroll
        for (int off = 1; off < 32; off <<= 1) {
            int v = __shfl_up_sync(0xffffffffu, w, off);
            if (lane >= off) w += v;
        }
        wsum[lane] = w;
    }
    __syncthreads();
    int off = (wid ? wsum[wid - 1] : 0) + incl - s;
#pragma unroll
    for (int i = 0; i < 10; i++) {
        int idx = base + i;
        if (idx < NN) {
            g_rowptr[idx] = off; off += c[i];
            g_dinv[idx] = rsqrtf((float)c[i] + 1.0f);
        }
    }
    if (t == 1023) g_rowptr[NN] = off;
}

__global__ void fill_edges_kernel() {
    int e = blockIdx.x * blockDim.x + threadIdx.x;
    if (e < EE) {
        int dst = g_dst[e];
        int pos = atomicAdd(&g_cursor[dst], 1);
        g_col[g_rowptr[dst] + pos] = g_src[e];
    }
}

// ---------------------------------------------------------------------------
// Conversions: fp32 -> fp16 hi/lo split, laid out along extended K
// ---------------------------------------------------------------------------
__device__ __forceinline__ void split2h(float a0, float a1,
                                        __half2& hh, __half2& ll) {
    __half h0 = __float2half_rn(a0), h1 = __float2half_rn(a1);
    __half l0 = __float2half_rn(a0 - __half2float(h0));
    __half l1 = __float2half_rn(a1 - __half2float(h1));
    hh = __halves2half2(h0, h1);
    ll = __halves2half2(l0, l1);
}

// x[10000,512] -> g_A2 rows [0,10240): pattern [hi | lo], pad rows = 0
__global__ void convx_kernel(const float* __restrict__ x) {
    int i = blockIdx.x * 256 + threadIdx.x;       // pair index
    int row = i >> 8, cp = i & 255;
    float a0 = 0.f, a1 = 0.f;
    if (row < NN) {
        float2 v = ((const float2*)x)[(size_t)row * 256 + cp];
        a0 = v.x; a1 = v.y;
    }
    __half2 hh, ll;
    split2h(a0, a1, hh, ll);
    size_t b = (size_t)row * KE2 + cp;
    g_A2[b] = hh; g_A2[b + 256] = ll;
}

// W1/W2 [512,512] (k-major rows) -> transposed split [hi | hi] in one launch
__global__ void convw_kernel(const float* __restrict__ W1,
                             const float* __restrict__ W2) {
    const int sel = blockIdx.x >> 9;              // 0 -> W1/B1, 1 -> W2/B2
    const float* __restrict__ W = sel ? W2 : W1;
    __half2* out = sel ? g_B2 : g_B1;
    int i = (blockIdx.x & 511) * 256 + threadIdx.x;   // (n, kp)
    int n = i >> 8, kp = i & 255;
    float a0 = W[(size_t)(2 * kp) * 512 + n];
    float a1 = W[(size_t)(2 * kp + 1) * 512 + n];
    __half h0 = __float2half_rn(a0), h1 = __float2half_rn(a1);
    __half2 hh = __halves2half2(h0, h1);
    size_t b = (size_t)n * KE2 + kp;
    out[b] = hh; out[b + 256] = hh;
}

// ---------------------------------------------------------------------------
// Warp-MMA GEMM, cp.async 3-stage pipeline:
// g_h[M,512] = A2 @ B^T over extended K=1024 (fp16 2-term split)
// CTA: 128x128 tile, 256 threads / 8 warps, warp tile 64x32 (4x4 m16n8k16).
// 16 K-chunks of 64 halves; stage = 32KB SW128-swizzled (A 16KB | B 16KB).
// ---------------------------------------------------------------------------
template <int WHICH>   // weight select: 1 -> g_B1, 2 -> g_B2
__global__ __launch_bounds__(256, 2)
void gemm_mma_kernel() {
    extern __shared__ __align__(1024) char sm[];
    const __half2* __restrict__ Bsel = (WHICH == 1) ? g_B1 : g_B2;

    const int tid = threadIdx.x;
    const int lane = tid & 31, wid = tid >> 5;
    const int warp_m = wid & 1;       // 2 m-blocks of 64
    const int warp_n = wid >> 1;      // 4 n-blocks of 32
    const int rowBase = blockIdx.x * 128;
    const int colBase = blockIdx.y * 128;

    // Cooperative load mapping: threads 0-127 -> A rows, 128-255 -> B rows.
    const int half = tid >> 7;
    const int lrow = tid & 127;
    const uint4* __restrict__ gsrc = half
        ? (const uint4*)(Bsel + (size_t)(colBase + lrow) * KE2)
        : (const uint4*)(g_A2 + (size_t)(rowBase + lrow) * KE2);

    const uint32_t smBase = smem_u32(sm);
    const uint32_t dstHalf = half * 16384u;

    // issue cp.async group for chunk c into stage c % STAGES
    auto issue = [&](int c) {
        uint32_t stage = smBase + (uint32_t)(c % STAGES) * STAGE_BYTES + dstHalf;
        const uint4* src = gsrc + c * 8;
#pragma unroll
        for (int j = 0; j < 8; j++)
            cp16(stage + swz128((uint32_t)(lrow * 128 + j * 16)), src + j);
        cp_commit();
    };

    float acc[4][4][4];
#pragma unroll
    for (int i = 0; i < 4; i++)
#pragma unroll
        for (int j = 0; j < 4; j++)
#pragma unroll
            for (int r = 0; r < 4; r++) acc[i][j][r] = 0.f;

    issue(0); issue(1);               // prologue: STAGES-1 groups in flight

    for (int c = 0; c < NCHUNK; c++) {
        if (c + STAGES - 1 < NCHUNK) cp_wait<STAGES - 2>();
        else                         cp_wait<0>();
        __syncthreads();
        if (c + STAGES - 1 < NCHUNK) issue(c + STAGES - 1);

        const uint32_t sA = smBase + (uint32_t)(c % STAGES) * STAGE_BYTES;
        const uint32_t sB = sA + 16384u;

#pragma unroll
        for (int ks = 0; ks < 4; ks++) {              // 4 x K=16
            const uint32_t kOff = ks * 32 + ((lane >> 4) * 16);
            uint32_t a[4][4];
#pragma unroll
            for (int mt = 0; mt < 4; mt++) {
                int r = warp_m * 64 + mt * 16 + (lane & 15);
                ldm_x4(a[mt][0], a[mt][1], a[mt][2], a[mt][3],
                       sA + swz128((uint32_t)(r * 128) + kOff));
            }
            uint32_t b[4][2];
#pragma unroll
            for (int p = 0; p < 2; p++) {             // 2 n-tile pairs
                int r = warp_n * 32 + p * 16 + (lane & 15);
                uint32_t t0, t1, t2, t3;
                ldm_x4(t0, t1, t2, t3, sB + swz128((uint32_t)(r * 128) + kOff));
                b[2 * p][0] = t0;      b[2 * p][1] = t2;
                b[2 * p + 1][0] = t1;  b[2 * p + 1][1] = t3;
            }
#pragma unroll
            for (int mt = 0; mt < 4; mt++)
#pragma unroll
                for (int nt = 0; nt < 4; nt++)
                    mma16816(acc[mt][nt], a[mt], b[nt]);
        }
        __syncthreads();
    }

    // Epilogue: fragment -> fp32 g_h
    const int g = lane >> 2, tig = lane & 3;
#pragma unroll
    for (int mt = 0; mt < 4; mt++) {
        const int row0 = rowBase + warp_m * 64 + mt * 16 + g;
#pragma unroll
        for (int nt = 0; nt < 4; nt++) {
            const int col = colBase + warp_n * 32 + nt * 8 + 2 * tig;
            if (row0 < NN)
                *(float2*)&g_h[(size_t)row0 * 512 + col] =
                    make_float2(acc[mt][nt][0], acc[mt][nt][1]);
            if (row0 + 8 < NN)
                *(float2*)&g_h[(size_t)(row0 + 8) * 512 + col] =
                    make_float2(acc[mt][nt][2], acc[mt][nt][3]);
        }
    }
}

// ---------------------------------------------------------------------------
// Aggregation: acc = dinv_i^2*h_i + b + sum dinv_i*dinv_s*h_s
// TO_A2: write relu + fp16 hi/lo split into g_A2 (feeds next GEMM)
// else:  write fp32 g_pre (feeds classifier)
// ---------------------------------------------------------------------------
template <bool TO_A2>
__global__ __launch_bounds__(128)
void aggregate_kernel(const float* __restrict__ bias) {
    const float* __restrict__ h = g_h;
    const int i = blockIdx.x;
    const int f = threadIdx.x * 4;
    const float di = g_dinv[i];

    float4 hv = *reinterpret_cast<const float4*>(&h[(size_t)i * 512 + f]);
    float4 bv = *reinterpret_cast<const float4*>(&bias[f]);
    const float w0 = di * di;
    float4 acc;
    acc.x = fmaf(w0, hv.x, bv.x);
    acc.y = fmaf(w0, hv.y, bv.y);
    acc.z = fmaf(w0, hv.z, bv.z);
    acc.w = fmaf(w0, hv.w, bv.w);

    const int s0 = g_rowptr[i];
    const int s1 = g_rowptr[i + 1];
    for (int e = s0; e < s1; e++) {
        int s = g_col[e];
        float w = di * g_dinv[s];
        float4 v = *reinterpret_cast<const float4*>(&h[(size_t)s * 512 + f]);
        acc.x = fmaf(w, v.x, acc.x);
        acc.y = fmaf(w, v.y, acc.y);
        acc.z = fmaf(w, v.z, acc.z);
        acc.w = fmaf(w, v.w, acc.w);
    }

    if (!TO_A2) {
        *reinterpret_cast<float4*>(&g_pre[(size_t)i * 512 + f]) = acc;
    } else {
        float r0 = fmaxf(acc.x, 0.f), r1 = fmaxf(acc.y, 0.f);
        float r2 = fmaxf(acc.z, 0.f), r3 = fmaxf(acc.w, 0.f);
        __half2 hh0, ll0, hh1, ll1;
        split2h(r0, r1, hh0, ll0);
        split2h(r2, r3, hh1, ll1);
        size_t b = (size_t)i * KE2 + (f >> 1);
        g_A2[b]       = hh0;  g_A2[b + 1]   = hh1;
        g_A2[b + 256] = ll0;  g_A2[b + 257] = ll1;
    }
}

// ---------------------------------------------------------------------------
// Final: out[N,16] = relu(g_pre) @ Wl + bl. Wl staged in smem; warp per row.
// ---------------------------------------------------------------------------
__global__ __launch_bounds__(256)
void final_kernel(const float* __restrict__ Wl, const float* __restrict__ bl,
                  float* __restrict__ out) {
    __shared__ __align__(16) float WlS[512 * 16];
    __shared__ float outS[8][16];
    const float* __restrict__ pre = g_pre;

    const int tid = threadIdx.x;
    for (int idx = tid; idx < 512 * 16 / 4; idx += 256)
        reinterpret_cast<float4*>(WlS)[idx] =
            reinterpret_cast<const float4*>(Wl)[idx];
    __syncthreads();

    const int w = tid >> 5;
    const int lane = tid & 31;
    const int row = blockIdx.x * 8 + w;
    if (row < NN) {
        float4 acc0 = make_float4(0.f, 0.f, 0.f, 0.f);
        float4 acc1 = acc0, acc2 = acc0, acc3 = acc0;
#pragma unroll
        for (int kk = 0; kk < 16; kk++) {
            int k = kk * 32 + lane;
            float a = fmaxf(pre[(size_t)row * 512 + k], 0.f);
            const float4* wrow = reinterpret_cast<const float4*>(&WlS[k * 16]);
            float4 w0 = wrow[0], w1 = wrow[1], w2 = wrow[2], w3 = wrow[3];
            acc0.x = fmaf(a, w0.x, acc0.x); acc0.y = fmaf(a, w0.y, acc0.y);
            acc0.z = fmaf(a, w0.z, acc0.z); acc0.w = fmaf(a, w0.w, acc0.w);
            acc1.x = fmaf(a, w1.x, acc1.x); acc1.y = fmaf(a, w1.y, acc1.y);
            acc1.z = fmaf(a, w1.z, acc1.z); acc1.w = fmaf(a, w1.w, acc1.w);
            acc2.x = fmaf(a, w2.x, acc2.x); acc2.y = fmaf(a, w2.y, acc2.y);
            acc2.z = fmaf(a, w2.z, acc2.z); acc2.w = fmaf(a, w2.w, acc2.w);
            acc3.x = fmaf(a, w3.x, acc3.x); acc3.y = fmaf(a, w3.y, acc3.y);
            acc3.z = fmaf(a, w3.z, acc3.z); acc3.w = fmaf(a, w3.w, acc3.w);
        }
#pragma unroll
        for (int off = 16; off > 0; off >>= 1) {
            acc0.x += __shfl_xor_sync(0xffffffff, acc0.x, off);
            acc0.y += __shfl_xor_sync(0xffffffff, acc0.y, off);
            acc0.z += __shfl_xor_sync(0xffffffff, acc0.z, off);
            acc0.w += __shfl_xor_sync(0xffffffff, acc0.w, off);
            acc1.x += __shfl_xor_sync(0xffffffff, acc1.x, off);
            acc1.y += __shfl_xor_sync(0xffffffff, acc1.y, off);
            acc1.z += __shfl_xor_sync(0xffffffff, acc1.z, off);
            acc1.w += __shfl_xor_sync(0xffffffff, acc1.w, off);
            acc2.x += __shfl_xor_sync(0xffffffff, acc2.x, off);
            acc2.y += __shfl_xor_sync(0xffffffff, acc2.y, off);
            acc2.z += __shfl_xor_sync(0xffffffff, acc2.z, off);
            acc2.w += __shfl_xor_sync(0xffffffff, acc2.w, off);
            acc3.x += __shfl_xor_sync(0xffffffff, acc3.x, off);
            acc3.y += __shfl_xor_sync(0xffffffff, acc3.y, off);
            acc3.z += __shfl_xor_sync(0xffffffff, acc3.z, off);
            acc3.w += __shfl_xor_sync(0xffffffff, acc3.w, off);
        }
        if (lane == 0) {
            *reinterpret_cast<float4*>(&outS[w][0])  = acc0;
            *reinterpret_cast<float4*>(&outS[w][4])  = acc1;
            *reinterpret_cast<float4*>(&outS[w][8])  = acc2;
            *reinterpret_cast<float4*>(&outS[w][12]) = acc3;
        }
        __syncwarp();
        if (lane < 16)
            out[(size_t)row * 16 + lane] = outS[w][lane] + bl[lane];
    }
}

// ---------------------------------------------------------------------------
// Launch — kernel launches + one idempotent attribute set (not a stream op)
// ---------------------------------------------------------------------------
extern "C" void kernel_launch(void* const* d_in, const int* in_sizes, int n_in,
                              void* d_out, int out_size) {
    const float* x  = (const float*)d_in[0];
    const void*  ei = d_in[1];
    const float* W1 = (const float*)d_in[2];
    const float* b1 = (const float*)d_in[3];
    const float* W2 = (const float*)d_in[4];
    const float* b2 = (const float*)d_in[5];
    const float* Wl = (const float*)d_in[6];
    const float* bl = (const float*)d_in[7];
    float* out = (float*)d_out;

    cudaFuncSetAttribute(gemm_mma_kernel<1>,
                         cudaFuncAttributeMaxDynamicSharedMemorySize, GEMM_DSMEM);
    cudaFuncSetAttribute(gemm_mma_kernel<2>,
                         cudaFuncAttributeMaxDynamicSharedMemorySize, GEMM_DSMEM);

    // CSR build + degrees (dinv fused into scan)
    detect_kernel<<<1, 256>>>((const int*)ei);
    init_counts_kernel<<<(NN + 255) / 256, 256>>>();
    decode_count_kernel<<<(EE + 255) / 256, 256>>>(ei);
    scan_kernel<<<1, 1024>>>();
    fill_edges_kernel<<<(EE + 255) / 256, 256>>>();

    // fp16 split operand prep (both weight matrices in one launch)
    convx_kernel<<<MPAD, 256>>>(x);
    convw_kernel<<<1024, 256>>>(W1, W2);

    dim3 gemmGrid(MPAD / 128, 4);   // (80, 4)

    // Layer 1
    gemm_mma_kernel<1><<<gemmGrid, 256, GEMM_DSMEM>>>();
    aggregate_kernel<true><<<NN, 128>>>(b1);     // relu+split -> g_A2
    // Layer 2
    gemm_mma_kernel<2><<<gemmGrid, 256, GEMM_DSMEM>>>();
    aggregate_kernel<false><<<NN, 128>>>(b2);    // fp32 -> g_pre
    // Classifier
    final_kernel<<<(NN + 7) / 8, 256>>>(Wl, bl, out);
}